// round 13
// baseline (speedup 1.0000x reference)
#include <cuda_runtime.h>
#include <cuda_bf16.h>
#include <math.h>
#include <stdint.h>

// MonotonicNN via HMMA bf16: s-pairing + R6 geometry (16 warps: 8 m-strips x
// 2 n-halves), ks-outer GEMM loops, L1 fused per k-chunk, L2->L3 through
// swizzled smem A-tiles (one per s). Registers ~115/thread -> 4 warps/SMSP.
// Every addressing pattern validated in R5-R9 runs.

#define NTHR  512
#define TM    128
#define NS    51
#define NB    50
#define BATCH 16384
#define HID   128

// weight/A tile: 128 rows x 256 B; row-swizzled chunks of 16B
#define TILE_B   32768
#define OFF_W2   0
#define OFF_W3   (1 * TILE_B)
#define OFF_A0   (2 * TILE_B)
#define OFF_A1   (3 * TILE_B)
#define OFF_MISC (4 * TILE_B)   // 131072
// float-indexed misc: [0,256) W1 | [256,384) B1 | [384,512) B2 | [512,640) B3
// [640,768) W4 | [768,896) X | [896,1024) H | [1024,1076) CCW(52) | [1076] b4
// [1080,1336) sP0 | [1336,1592) sP1
#define SMEM_TOTAL (OFF_MISC + 1600 * 4)

__device__ __forceinline__ void mma_bf16(float* c, const uint32_t* a,
                                         uint32_t b0, uint32_t b1) {
    asm volatile(
        "mma.sync.aligned.m16n8k16.row.col.f32.bf16.bf16.f32 "
        "{%0,%1,%2,%3}, {%4,%5,%6,%7}, {%8,%9}, {%0,%1,%2,%3};"
        : "+f"(c[0]), "+f"(c[1]), "+f"(c[2]), "+f"(c[3])
        : "r"(a[0]), "r"(a[1]), "r"(a[2]), "r"(a[3]), "r"(b0), "r"(b1));
}

#define LDSM_X4(r, addr) \
    asm volatile("ldmatrix.sync.aligned.m8n8.x4.shared.b16 {%0,%1,%2,%3}, [%4];" \
        : "=r"((r)[0]), "=r"((r)[1]), "=r"((r)[2]), "=r"((r)[3]) : "r"(addr))

__device__ __forceinline__ uint32_t smem_to_u32(const void* p) {
    uint32_t a;
    asm("{ .reg .u64 t; cvta.to.shared.u64 t, %1; cvt.u32.u64 %0, t; }" : "=r"(a) : "l"(p));
    return a;
}

// pack two fp32 -> bf16x2 (v0 in low half)
__device__ __forceinline__ uint32_t pack_bf16(float v0, float v1) {
    uint32_t r;
    asm("cvt.rn.bf16x2.f32 %0, %1, %2;" : "=r"(r) : "f"(v1), "f"(v0));
    return r;
}

__global__ void __launch_bounds__(NTHR, 1)
monnn_kernel(const float* __restrict__ x,  const float* __restrict__ h,
             const float* __restrict__ w1, const float* __restrict__ b1,
             const float* __restrict__ w2, const float* __restrict__ b2,
             const float* __restrict__ w3, const float* __restrict__ b3,
             const float* __restrict__ w4, const float* __restrict__ b4,
             float* __restrict__ out) {
    extern __shared__ char smem[];
    float* FM  = (float*)(smem + OFF_MISC);
    float* sW1 = FM;          float* sB1 = FM + 256;
    float* sB2 = FM + 384;    float* sB3 = FM + 512;
    float* sW4 = FM + 640;    float* sX  = FM + 768;
    float* sH  = FM + 896;    float* sCCW = FM + 1024;  // 52 entries
    float* sP0 = FM + 1080;   // [128][2] partials for s0
    float* sP1 = FM + 1336;   // [128][2] partials for s1

    const int tid  = threadIdx.x;
    const int wid  = tid >> 5;
    const int lane = tid & 31;
    const int mbase = (wid & 7) * 16;     // warp m-strip
    const int nh    = wid >> 3;           // n-half 0/1
    const int nbase = nh * 64;
    const int bbase = blockIdx.x * TM;

    // ---- prologue: misc params ----
    if (tid < 256) sW1[tid] = w1[tid];
    if (tid < 128) {
        sB1[tid] = b1[tid]; sB2[tid] = b2[tid]; sB3[tid] = b3[tid];
        sW4[tid] = w4[tid];
        sX[tid] = x[bbase + tid]; sH[tid] = h[bbase + tid];
    }
    if (tid < 52) {  // Clenshaw-Curtis weights; [51]=0 pads the odd pair
        float acw = 0.0f;
        if (tid <= NB) {
            #pragma unroll 1
            for (int i = 0; i <= NB; i++) {
                float Wi = (i == 0) ? 1.0f : ((i & 1) ? 0.0f : 2.0f / (1.0f - (float)(i * i)));
                acw = fmaf(cospif((float)(i * tid) / (float)NB), Wi, acw);
            }
            acw *= 2.0f / (float)NB;
            if (tid == 0 || tid == NB) acw *= 0.5f;
        }
        sCCW[tid] = acw;
    }
    if (tid == 0) FM[1076] = b4[0];

    // ---- prologue: W2,W3 -> transposed bf16 swizzled tiles Wt[j][k] ----
    for (int t = tid; t < 2 * 8192; t += NTHR) {
        int mtx = t >> 13;
        int r   = t & 8191;
        int kp  = r >> 7;           // k-pair index
        int j   = r & 127;
        int k   = kp * 2;
        const float* W = mtx ? w3 : w2;
        float v0 = W[k * 128 + j];
        float v1 = W[(k + 1) * 128 + j];
        uint32_t hp = pack_bf16(v0, v1);
        uint32_t off = (mtx ? OFF_W3 : OFF_W2)
                     + (uint32_t)j * 256u
                     + 16u * ((uint32_t)(k >> 3) ^ (uint32_t)(j & 7))
                     + (uint32_t)(kp & 3) * 4u;
        *(uint32_t*)(smem + off) = hp;
    }
    __syncthreads();

    // ---- per-thread constants (all validated R5-R9) ----
    const int r0 = mbase + (lane >> 2);        // frag row 0
    const int r1 = r0 + 8;                     // frag row 1
    const int kq = (lane & 3) * 2;             // frag col/k pair base
    const float xm0 = sX[r0], xm1 = sX[r1];
    const float hm0 = sH[r0], hm1 = sH[r1];
    const float b4v = FM[1076];
    const uint32_t sb = smem_to_u32(smem);
    const int lane7 = lane & 7;
    // B-ldmatrix lane constants
    const uint32_t nB  = (uint32_t)(nbase + 8 * ((lane >> 3) >> 1) + lane7);
    const uint32_t n7B = nB & 7u;
    const uint32_t cB  = (uint32_t)((lane >> 3) & 1);
    const uint32_t rowB = nB * 256u;           // + g*4096
    // A-ldmatrix lane constants
    const uint32_t rA   = (uint32_t)(mbase + ((lane >> 3) & 1) * 8 + lane7);
    const uint32_t rowA = rA * 256u;
    const uint32_t cA   = (uint32_t)(lane >> 4);
    // A-store swizzle constants
    const uint32_t swS_base = (uint32_t)(lane >> 2);
    const uint32_t swS_q    = (uint32_t)(lane & 3) * 4u;

    float zacc = 0.0f;   // meaningful for tid < 128

    #pragma unroll 1
    for (int sp = 0; sp < 26; sp++) {
        const int s0 = 2 * sp, s1 = 2 * sp + 1;
        const float tS0 = (cospif((float)s0 / (float)NB) + 1.0f) * 0.5f;
        const float tS1 = (cospif((float)s1 / (float)NB) + 1.0f) * 0.5f;
        const float xs00 = xm0 * tS0, xs01 = xm1 * tS0;
        const float xs10 = xm0 * tS1, xs11 = xm1 * tS1;

        // acc[2t+ss][4]: n-tile t (0..7) of this warp's half, s-chain ss
        float acc[16][4];
        #pragma unroll
        for (int i = 0; i < 16; i++)
            #pragma unroll
            for (int q = 0; q < 4; q++) acc[i][q] = 0.0f;

        // ========== layer 2: ks-outer, L1 fused per chunk ==========
        #pragma unroll 1
        for (int ks = 0; ks < 8; ks++) {
            uint32_t aIn0[4], aIn1[4];
            #pragma unroll
            for (int j = 0; j < 2; j++) {
                int k = ks * 16 + kq + 8 * j;
                float2 wa = *(const float2*)&sW1[k];
                float2 wb = *(const float2*)&sW1[128 + k];
                float2 bb = *(const float2*)&sB1[k];
                float c0x = fmaf(hm0, wb.x, bb.x), c0y = fmaf(hm0, wb.y, bb.y);
                float c1x = fmaf(hm1, wb.x, bb.x), c1y = fmaf(hm1, wb.y, bb.y);
                aIn0[2*j]     = pack_bf16(fmaxf(fmaf(xs00, wa.x, c0x), 0.0f),
                                          fmaxf(fmaf(xs00, wa.y, c0y), 0.0f));
                aIn0[2*j + 1] = pack_bf16(fmaxf(fmaf(xs01, wa.x, c1x), 0.0f),
                                          fmaxf(fmaf(xs01, wa.y, c1y), 0.0f));
                aIn1[2*j]     = pack_bf16(fmaxf(fmaf(xs10, wa.x, c0x), 0.0f),
                                          fmaxf(fmaf(xs10, wa.y, c0y), 0.0f));
                aIn1[2*j + 1] = pack_bf16(fmaxf(fmaf(xs11, wa.x, c1x), 0.0f),
                                          fmaxf(fmaf(xs11, wa.y, c1y), 0.0f));
            }
            const uint32_t swb = (((uint32_t)(2 * ks) + cB) ^ n7B) * 16u;
            #pragma unroll
            for (int g = 0; g < 4; g++) {
                uint32_t bq[4];
                LDSM_X4(bq, sb + OFF_W2 + rowB + (uint32_t)g * 4096u + swb);
                mma_bf16(acc[4*g    ], aIn0, bq[0], bq[1]);
                mma_bf16(acc[4*g + 1], aIn1, bq[0], bq[1]);
                mma_bf16(acc[4*g + 2], aIn0, bq[2], bq[3]);
                mma_bf16(acc[4*g + 3], aIn1, bq[2], bq[3]);
            }
        }

        __syncthreads();  // prev iter: L3 A-reads + sP combine complete

        // ---- L2 epilogue: relu(D+b2) -> swizzled smem A-tiles (per s) ----
        #pragma unroll
        for (int t = 0; t < 8; t++) {
            int n0 = nbase + 8 * t + kq;
            float2 b2v = *(const float2*)&sB2[n0];
            uint32_t sw = ((uint32_t)(8 * nh + t) ^ swS_base) * 16u + swS_q;
            const float* A0 = acc[2 * t];       // s0
            const float* A1 = acc[2 * t + 1];   // s1
            *(uint32_t*)(smem + OFF_A0 + (uint32_t)r0 * 256u + sw) =
                pack_bf16(fmaxf(A0[0] + b2v.x, 0.0f), fmaxf(A0[1] + b2v.y, 0.0f));
            *(uint32_t*)(smem + OFF_A0 + (uint32_t)r1 * 256u + sw) =
                pack_bf16(fmaxf(A0[2] + b2v.x, 0.0f), fmaxf(A0[3] + b2v.y, 0.0f));
            *(uint32_t*)(smem + OFF_A1 + (uint32_t)r0 * 256u + sw) =
                pack_bf16(fmaxf(A1[0] + b2v.x, 0.0f), fmaxf(A1[1] + b2v.y, 0.0f));
            *(uint32_t*)(smem + OFF_A1 + (uint32_t)r1 * 256u + sw) =
                pack_bf16(fmaxf(A1[2] + b2v.x, 0.0f), fmaxf(A1[3] + b2v.y, 0.0f));
        }
        __syncthreads();  // A-tiles visible

        #pragma unroll
        for (int i = 0; i < 16; i++)
            #pragma unroll
            for (int q = 0; q < 4; q++) acc[i][q] = 0.0f;

        // ========== layer 3: ks-outer, A via ldmatrix from smem ==========
        #pragma unroll 1
        for (int ks = 0; ks < 8; ks++) {
            const uint32_t swa = (((uint32_t)(2 * ks) + cA) ^ (uint32_t)lane7) * 16u;
            uint32_t a0[4], a1[4];
            LDSM_X4(a0, sb + OFF_A0 + rowA + swa);
            LDSM_X4(a1, sb + OFF_A1 + rowA + swa);
            const uint32_t swb = (((uint32_t)(2 * ks) + cB) ^ n7B) * 16u;
            #pragma unroll
            for (int g = 0; g < 4; g++) {
                uint32_t bq[4];
                LDSM_X4(bq, sb + OFF_W3 + rowB + (uint32_t)g * 4096u + swb);
                mma_bf16(acc[4*g    ], a0, bq[0], bq[1]);
                mma_bf16(acc[4*g + 1], a1, bq[0], bq[1]);
                mma_bf16(acc[4*g + 2], a0, bq[2], bq[3]);
                mma_bf16(acc[4*g + 3], a1, bq[2], bq[3]);
            }
        }

        // ---- layer 4 partials (this warp's n-half) ----
        float p00 = 0.0f, p01 = 0.0f, p10 = 0.0f, p11 = 0.0f;
        #pragma unroll
        for (int t = 0; t < 8; t++) {
            int n0 = nbase + 8 * t + kq;
            float2 b3v = *(const float2*)&sB3[n0];
            float2 w4v = *(const float2*)&sW4[n0];
            const float* A0 = acc[2 * t];
            const float* A1 = acc[2 * t + 1];
            p00 = fmaf(fmaxf(A0[0] + b3v.x, 0.0f), w4v.x, p00);
            p00 = fmaf(fmaxf(A0[1] + b3v.y, 0.0f), w4v.y, p00);
            p01 = fmaf(fmaxf(A0[2] + b3v.x, 0.0f), w4v.x, p01);
            p01 = fmaf(fmaxf(A0[3] + b3v.y, 0.0f), w4v.y, p01);
            p10 = fmaf(fmaxf(A1[0] + b3v.x, 0.0f), w4v.x, p10);
            p10 = fmaf(fmaxf(A1[1] + b3v.y, 0.0f), w4v.y, p10);
            p11 = fmaf(fmaxf(A1[2] + b3v.x, 0.0f), w4v.x, p11);
            p11 = fmaf(fmaxf(A1[3] + b3v.y, 0.0f), w4v.y, p11);
        }
        p00 += __shfl_xor_sync(0xFFFFFFFFu, p00, 1);
        p00 += __shfl_xor_sync(0xFFFFFFFFu, p00, 2);
        p01 += __shfl_xor_sync(0xFFFFFFFFu, p01, 1);
        p01 += __shfl_xor_sync(0xFFFFFFFFu, p01, 2);
        p10 += __shfl_xor_sync(0xFFFFFFFFu, p10, 1);
        p10 += __shfl_xor_sync(0xFFFFFFFFu, p10, 2);
        p11 += __shfl_xor_sync(0xFFFFFFFFu, p11, 1);
        p11 += __shfl_xor_sync(0xFFFFFFFFu, p11, 2);

        if ((lane & 3) == 0) {
            sP0[r0 * 2 + nh] = p00;
            sP0[r1 * 2 + nh] = p01;
            sP1[r0 * 2 + nh] = p10;
            sP1[r1 * 2 + nh] = p11;
        }
        __syncthreads();  // sP visible (A-reads also done -> safe to overwrite next iter)

        if (tid < 128) {
            const float ccw0 = sCCW[s0], ccw1 = sCCW[s1];
            float v0 = sP0[tid * 2] + sP0[tid * 2 + 1] + b4v;
            float v1 = sP1[tid * 2] + sP1[tid * 2 + 1] + b4v;
            float e0 = (v0 > 0.0f) ? v0 : expm1f(v0);
            float e1 = (v1 > 0.0f) ? v1 : expm1f(v1);
            zacc = fmaf(ccw0, e0 + 1.0f, zacc);
            zacc = fmaf(ccw1, e1 + 1.0f, zacc);
        }
        // combine finishes before next iter's sync2 -> no extra barrier needed
    }

    if (tid < 128)
        out[bbase + tid] = fmaf(zacc, 0.5f * sX[tid], sH[tid]);
}

extern "C" void kernel_launch(void* const* d_in, const int* in_sizes, int n_in,
                              void* d_out, int out_size) {
    const float* x  = (const float*)d_in[0];
    const float* h  = (const float*)d_in[1];
    const float* w1 = (const float*)d_in[2];
    const float* b1 = (const float*)d_in[3];
    const float* w2 = (const float*)d_in[4];
    const float* b2 = (const float*)d_in[5];
    const float* w3 = (const float*)d_in[6];
    const float* b3 = (const float*)d_in[7];
    const float* w4 = (const float*)d_in[8];
    const float* b4 = (const float*)d_in[9];
    float* out = (float*)d_out;

    static int attr_set = 0;
    if (!attr_set) {
        cudaFuncSetAttribute(monnn_kernel,
                             cudaFuncAttributeMaxDynamicSharedMemorySize, SMEM_TOTAL);
        attr_set = 1;
    }
    monnn_kernel<<<BATCH / TM, NTHR, SMEM_TOTAL>>>(x, h, w1, b1, w2, b2, w3, b3, w4, b4, out);
}

// round 14
// speedup vs baseline: 1.0774x; 1.0774x over previous
#include <cuda_runtime.h>
#include <cuda_bf16.h>
#include <math.h>
#include <stdint.h>

// MonotonicNN via HMMA bf16: s-pairing + 16 warps (8 m-strips x 2 n-halves),
// L2->L3 via swizzled smem A-tiles. R14: all in-loop synchronization is
// PAIRWISE (named bar.sync, 64 threads: warps w and w+8) -- the A-tile rows
// and partial sums of m-strip w are touched only by that pair. 8 pairs drift
// independently; bubbles overlap. Combine done by nh=0 warp of each pair.

#define NTHR  512
#define TM    128
#define NS    51
#define NB    50
#define BATCH 16384
#define HID   128

// weight/A tile: 128 rows x 256 B; row-swizzled chunks of 16B
#define TILE_B   32768
#define OFF_W2   0
#define OFF_W3   (1 * TILE_B)
#define OFF_A0   (2 * TILE_B)
#define OFF_A1   (3 * TILE_B)
#define OFF_MISC (4 * TILE_B)   // 131072
// float-indexed misc: [0,256) W1 | [256,384) B1 | [384,512) B2 | [512,640) B3
// [640,768) W4 | [768,896) X | [896,1024) H | [1024,1076) CCW(52) | [1076] b4
// [1080,1336) sP0 | [1336,1592) sP1
#define SMEM_TOTAL (OFF_MISC + 1600 * 4)

__device__ __forceinline__ void mma_bf16(float* c, const uint32_t* a,
                                         uint32_t b0, uint32_t b1) {
    asm volatile(
        "mma.sync.aligned.m16n8k16.row.col.f32.bf16.bf16.f32 "
        "{%0,%1,%2,%3}, {%4,%5,%6,%7}, {%8,%9}, {%0,%1,%2,%3};"
        : "+f"(c[0]), "+f"(c[1]), "+f"(c[2]), "+f"(c[3])
        : "r"(a[0]), "r"(a[1]), "r"(a[2]), "r"(a[3]), "r"(b0), "r"(b1));
}

#define LDSM_X4(r, addr) \
    asm volatile("ldmatrix.sync.aligned.m8n8.x4.shared.b16 {%0,%1,%2,%3}, [%4];" \
        : "=r"((r)[0]), "=r"((r)[1]), "=r"((r)[2]), "=r"((r)[3]) : "r"(addr))

// pairwise named barrier: warps w and w+8 (64 threads), ids 1..8
#define BAR_PAIR(id) \
    asm volatile("bar.sync %0, 64;" :: "r"(id) : "memory")

__device__ __forceinline__ uint32_t smem_to_u32(const void* p) {
    uint32_t a;
    asm("{ .reg .u64 t; cvta.to.shared.u64 t, %1; cvt.u32.u64 %0, t; }" : "=r"(a) : "l"(p));
    return a;
}

// pack two fp32 -> bf16x2 (v0 in low half)
__device__ __forceinline__ uint32_t pack_bf16(float v0, float v1) {
    uint32_t r;
    asm("cvt.rn.bf16x2.f32 %0, %1, %2;" : "=r"(r) : "f"(v1), "f"(v0));
    return r;
}

__global__ void __launch_bounds__(NTHR, 1)
monnn_kernel(const float* __restrict__ x,  const float* __restrict__ h,
             const float* __restrict__ w1, const float* __restrict__ b1,
             const float* __restrict__ w2, const float* __restrict__ b2,
             const float* __restrict__ w3, const float* __restrict__ b3,
             const float* __restrict__ w4, const float* __restrict__ b4,
             float* __restrict__ out) {
    extern __shared__ char smem[];
    float* FM  = (float*)(smem + OFF_MISC);
    float* sW1 = FM;          float* sB1 = FM + 256;
    float* sB2 = FM + 384;    float* sB3 = FM + 512;
    float* sW4 = FM + 640;    float* sX  = FM + 768;
    float* sH  = FM + 896;    float* sCCW = FM + 1024;  // 52 entries
    float* sP0 = FM + 1080;   // [128][2] partials for s0
    float* sP1 = FM + 1336;   // [128][2] partials for s1

    const int tid  = threadIdx.x;
    const int wid  = tid >> 5;
    const int lane = tid & 31;
    const int mbase = (wid & 7) * 16;     // warp m-strip
    const int nh    = wid >> 3;           // n-half 0/1
    const int nbase = nh * 64;
    const int bbase = blockIdx.x * TM;
    const int pbar  = (wid & 7) + 1;      // pair barrier id (1..8)

    // ---- prologue: misc params ----
    if (tid < 256) sW1[tid] = w1[tid];
    if (tid < 128) {
        sB1[tid] = b1[tid]; sB2[tid] = b2[tid]; sB3[tid] = b3[tid];
        sW4[tid] = w4[tid];
        sX[tid] = x[bbase + tid]; sH[tid] = h[bbase + tid];
    }
    if (tid < 52) {  // Clenshaw-Curtis weights; [51]=0 pads the odd pair
        float acw = 0.0f;
        if (tid <= NB) {
            #pragma unroll 1
            for (int i = 0; i <= NB; i++) {
                float Wi = (i == 0) ? 1.0f : ((i & 1) ? 0.0f : 2.0f / (1.0f - (float)(i * i)));
                acw = fmaf(cospif((float)(i * tid) / (float)NB), Wi, acw);
            }
            acw *= 2.0f / (float)NB;
            if (tid == 0 || tid == NB) acw *= 0.5f;
        }
        sCCW[tid] = acw;
    }
    if (tid == 0) FM[1076] = b4[0];

    // ---- prologue: W2,W3 -> transposed bf16 swizzled tiles Wt[j][k] ----
    for (int t = tid; t < 2 * 8192; t += NTHR) {
        int mtx = t >> 13;
        int r   = t & 8191;
        int kp  = r >> 7;           // k-pair index
        int j   = r & 127;
        int k   = kp * 2;
        const float* W = mtx ? w3 : w2;
        float v0 = W[k * 128 + j];
        float v1 = W[(k + 1) * 128 + j];
        uint32_t hp = pack_bf16(v0, v1);
        uint32_t off = (mtx ? OFF_W3 : OFF_W2)
                     + (uint32_t)j * 256u
                     + 16u * ((uint32_t)(k >> 3) ^ (uint32_t)(j & 7))
                     + (uint32_t)(kp & 3) * 4u;
        *(uint32_t*)(smem + off) = hp;
    }
    __syncthreads();

    // ---- per-thread constants (all validated R5-R13) ----
    const int r0 = mbase + (lane >> 2);        // frag row 0
    const int r1 = r0 + 8;                     // frag row 1
    const int kq = (lane & 3) * 2;             // frag col/k pair base
    const float xm0 = sX[r0], xm1 = sX[r1];
    const float hm0 = sH[r0], hm1 = sH[r1];
    const float b4v = FM[1076];
    const uint32_t sb = smem_to_u32(smem);
    const int lane7 = lane & 7;
    // B-ldmatrix lane constants
    const uint32_t nB  = (uint32_t)(nbase + 8 * ((lane >> 3) >> 1) + lane7);
    const uint32_t n7B = nB & 7u;
    const uint32_t cB  = (uint32_t)((lane >> 3) & 1);
    const uint32_t rowB = nB * 256u;           // + g*4096
    // A-ldmatrix lane constants
    const uint32_t rA   = (uint32_t)(mbase + ((lane >> 3) & 1) * 8 + lane7);
    const uint32_t rowA = rA * 256u;
    const uint32_t cA   = (uint32_t)(lane >> 4);
    // A-store swizzle constants
    const uint32_t swS_base = (uint32_t)(lane >> 2);
    const uint32_t swS_q    = (uint32_t)(lane & 3) * 4u;

    float zacc0 = 0.0f, zacc1 = 0.0f;   // meaningful in nh=0 warps

    #pragma unroll 1
    for (int sp = 0; sp < 26; sp++) {
        const int s0 = 2 * sp, s1 = 2 * sp + 1;
        const float tS0 = (cospif((float)s0 / (float)NB) + 1.0f) * 0.5f;
        const float tS1 = (cospif((float)s1 / (float)NB) + 1.0f) * 0.5f;
        const float xs00 = xm0 * tS0, xs01 = xm1 * tS0;
        const float xs10 = xm0 * tS1, xs11 = xm1 * tS1;

        // acc[2t+ss][4]: n-tile t (0..7) of this warp's half, s-chain ss
        float acc[16][4];
        #pragma unroll
        for (int i = 0; i < 16; i++)
            #pragma unroll
            for (int q = 0; q < 4; q++) acc[i][q] = 0.0f;

        // ========== layer 2: ks-outer, L1 fused per chunk ==========
        #pragma unroll 1
        for (int ks = 0; ks < 8; ks++) {
            uint32_t aIn0[4], aIn1[4];
            #pragma unroll
            for (int j = 0; j < 2; j++) {
                int k = ks * 16 + kq + 8 * j;
                float2 wa = *(const float2*)&sW1[k];
                float2 wb = *(const float2*)&sW1[128 + k];
                float2 bb = *(const float2*)&sB1[k];
                float c0x = fmaf(hm0, wb.x, bb.x), c0y = fmaf(hm0, wb.y, bb.y);
                float c1x = fmaf(hm1, wb.x, bb.x), c1y = fmaf(hm1, wb.y, bb.y);
                aIn0[2*j]     = pack_bf16(fmaxf(fmaf(xs00, wa.x, c0x), 0.0f),
                                          fmaxf(fmaf(xs00, wa.y, c0y), 0.0f));
                aIn0[2*j + 1] = pack_bf16(fmaxf(fmaf(xs01, wa.x, c1x), 0.0f),
                                          fmaxf(fmaf(xs01, wa.y, c1y), 0.0f));
                aIn1[2*j]     = pack_bf16(fmaxf(fmaf(xs10, wa.x, c0x), 0.0f),
                                          fmaxf(fmaf(xs10, wa.y, c0y), 0.0f));
                aIn1[2*j + 1] = pack_bf16(fmaxf(fmaf(xs11, wa.x, c1x), 0.0f),
                                          fmaxf(fmaf(xs11, wa.y, c1y), 0.0f));
            }
            const uint32_t swb = (((uint32_t)(2 * ks) + cB) ^ n7B) * 16u;
            #pragma unroll
            for (int g = 0; g < 4; g++) {
                uint32_t bq[4];
                LDSM_X4(bq, sb + OFF_W2 + rowB + (uint32_t)g * 4096u + swb);
                mma_bf16(acc[4*g    ], aIn0, bq[0], bq[1]);
                mma_bf16(acc[4*g + 1], aIn1, bq[0], bq[1]);
                mma_bf16(acc[4*g + 2], aIn0, bq[2], bq[3]);
                mma_bf16(acc[4*g + 3], aIn1, bq[2], bq[3]);
            }
        }

        BAR_PAIR(pbar);  // pair: prev-iter L3 A-reads + combine done

        // ---- L2 epilogue: relu(D+b2) -> swizzled smem A-tiles (per s) ----
        #pragma unroll
        for (int t = 0; t < 8; t++) {
            int n0 = nbase + 8 * t + kq;
            float2 b2v = *(const float2*)&sB2[n0];
            uint32_t sw = ((uint32_t)(8 * nh + t) ^ swS_base) * 16u + swS_q;
            const float* A0 = acc[2 * t];       // s0
            const float* A1 = acc[2 * t + 1];   // s1
            *(uint32_t*)(smem + OFF_A0 + (uint32_t)r0 * 256u + sw) =
                pack_bf16(fmaxf(A0[0] + b2v.x, 0.0f), fmaxf(A0[1] + b2v.y, 0.0f));
            *(uint32_t*)(smem + OFF_A0 + (uint32_t)r1 * 256u + sw) =
                pack_bf16(fmaxf(A0[2] + b2v.x, 0.0f), fmaxf(A0[3] + b2v.y, 0.0f));
            *(uint32_t*)(smem + OFF_A1 + (uint32_t)r0 * 256u + sw) =
                pack_bf16(fmaxf(A1[0] + b2v.x, 0.0f), fmaxf(A1[1] + b2v.y, 0.0f));
            *(uint32_t*)(smem + OFF_A1 + (uint32_t)r1 * 256u + sw) =
                pack_bf16(fmaxf(A1[2] + b2v.x, 0.0f), fmaxf(A1[3] + b2v.y, 0.0f));
        }
        BAR_PAIR(pbar);  // pair: A-tile rows [mbase,mbase+16) visible

        #pragma unroll
        for (int i = 0; i < 16; i++)
            #pragma unroll
            for (int q = 0; q < 4; q++) acc[i][q] = 0.0f;

        // ========== layer 3: ks-outer, A via ldmatrix from smem ==========
        #pragma unroll 1
        for (int ks = 0; ks < 8; ks++) {
            const uint32_t swa = (((uint32_t)(2 * ks) + cA) ^ (uint32_t)lane7) * 16u;
            uint32_t a0[4], a1[4];
            LDSM_X4(a0, sb + OFF_A0 + rowA + swa);
            LDSM_X4(a1, sb + OFF_A1 + rowA + swa);
            const uint32_t swb = (((uint32_t)(2 * ks) + cB) ^ n7B) * 16u;
            #pragma unroll
            for (int g = 0; g < 4; g++) {
                uint32_t bq[4];
                LDSM_X4(bq, sb + OFF_W3 + rowB + (uint32_t)g * 4096u + swb);
                mma_bf16(acc[4*g    ], a0, bq[0], bq[1]);
                mma_bf16(acc[4*g + 1], a1, bq[0], bq[1]);
                mma_bf16(acc[4*g + 2], a0, bq[2], bq[3]);
                mma_bf16(acc[4*g + 3], a1, bq[2], bq[3]);
            }
        }

        // ---- layer 4 partials (this warp's n-half) ----
        float p00 = 0.0f, p01 = 0.0f, p10 = 0.0f, p11 = 0.0f;
        #pragma unroll
        for (int t = 0; t < 8; t++) {
            int n0 = nbase + 8 * t + kq;
            float2 b3v = *(const float2*)&sB3[n0];
            float2 w4v = *(const float2*)&sW4[n0];
            const float* A0 = acc[2 * t];
            const float* A1 = acc[2 * t + 1];
            p00 = fmaf(fmaxf(A0[0] + b3v.x, 0.0f), w4v.x, p00);
            p00 = fmaf(fmaxf(A0[1] + b3v.y, 0.0f), w4v.y, p00);
            p01 = fmaf(fmaxf(A0[2] + b3v.x, 0.0f), w4v.x, p01);
            p01 = fmaf(fmaxf(A0[3] + b3v.y, 0.0f), w4v.y, p01);
            p10 = fmaf(fmaxf(A1[0] + b3v.x, 0.0f), w4v.x, p10);
            p10 = fmaf(fmaxf(A1[1] + b3v.y, 0.0f), w4v.y, p10);
            p11 = fmaf(fmaxf(A1[2] + b3v.x, 0.0f), w4v.x, p11);
            p11 = fmaf(fmaxf(A1[3] + b3v.y, 0.0f), w4v.y, p11);
        }
        p00 += __shfl_xor_sync(0xFFFFFFFFu, p00, 1);
        p00 += __shfl_xor_sync(0xFFFFFFFFu, p00, 2);
        p01 += __shfl_xor_sync(0xFFFFFFFFu, p01, 1);
        p01 += __shfl_xor_sync(0xFFFFFFFFu, p01, 2);
        p10 += __shfl_xor_sync(0xFFFFFFFFu, p10, 1);
        p10 += __shfl_xor_sync(0xFFFFFFFFu, p10, 2);
        p11 += __shfl_xor_sync(0xFFFFFFFFu, p11, 1);
        p11 += __shfl_xor_sync(0xFFFFFFFFu, p11, 2);

        if ((lane & 3) == 0) {
            sP0[r0 * 2 + nh] = p00;
            sP0[r1 * 2 + nh] = p01;
            sP1[r0 * 2 + nh] = p10;
            sP1[r1 * 2 + nh] = p11;
        }
        BAR_PAIR(pbar);  // pair: both n-halves' partials visible

        // ---- combine (nh=0 warp of pair; rows r0,r1, quad-redundant) ----
        if (nh == 0) {
            const float ccw0 = sCCW[s0], ccw1 = sCCW[s1];
            float v00 = sP0[r0 * 2] + sP0[r0 * 2 + 1] + b4v;
            float v01 = sP0[r1 * 2] + sP0[r1 * 2 + 1] + b4v;
            float v10 = sP1[r0 * 2] + sP1[r0 * 2 + 1] + b4v;
            float v11 = sP1[r1 * 2] + sP1[r1 * 2 + 1] + b4v;
            float e00 = (v00 > 0.0f) ? v00 : expm1f(v00);
            float e01 = (v01 > 0.0f) ? v01 : expm1f(v01);
            float e10 = (v10 > 0.0f) ? v10 : expm1f(v10);
            float e11 = (v11 > 0.0f) ? v11 : expm1f(v11);
            zacc0 = fmaf(ccw0, e00 + 1.0f, zacc0);
            zacc0 = fmaf(ccw1, e10 + 1.0f, zacc0);
            zacc1 = fmaf(ccw0, e01 + 1.0f, zacc1);
            zacc1 = fmaf(ccw1, e11 + 1.0f, zacc1);
        }
        // next iter's L2 ends with BAR_PAIR -> sP/A reuse is pair-safe
    }

    if (nh == 0 && (lane & 3) == 0) {
        out[bbase + r0] = fmaf(zacc0, 0.5f * xm0, hm0);
        out[bbase + r1] = fmaf(zacc1, 0.5f * xm1, hm1);
    }
}

extern "C" void kernel_launch(void* const* d_in, const int* in_sizes, int n_in,
                              void* d_out, int out_size) {
    const float* x  = (const float*)d_in[0];
    const float* h  = (const float*)d_in[1];
    const float* w1 = (const float*)d_in[2];
    const float* b1 = (const float*)d_in[3];
    const float* w2 = (const float*)d_in[4];
    const float* b2 = (const float*)d_in[5];
    const float* w3 = (const float*)d_in[6];
    const float* b3 = (const float*)d_in[7];
    const float* w4 = (const float*)d_in[8];
    const float* b4 = (const float*)d_in[9];
    float* out = (float*)d_out;

    static int attr_set = 0;
    if (!attr_set) {
        cudaFuncSetAttribute(monnn_kernel,
                             cudaFuncAttributeMaxDynamicSharedMemorySize, SMEM_TOTAL);
        attr_set = 1;
    }
    monnn_kernel<<<BATCH / TM, NTHR, SMEM_TOTAL>>>(x, h, w1, b1, w2, b2, w3, b3, w4, b4, out);
}

// round 15
// speedup vs baseline: 1.2551x; 1.1649x over previous
#include <cuda_runtime.h>
#include <cuda_bf16.h>
#include <math.h>
#include <stdint.h>

// MonotonicNN via HMMA bf16, s-pairing + ALL layers on tensor core.
// Base = R9 (165.6us best): 128 CTAs x 256 thr (8 warps, warp = m16 x n-full),
// two s-chains per warp, g2-blocked GEMMs (4 n-tiles/block, 32 acc regs).
// R15: L1 (K=2 GEMM) done via MMA with zero-padded W1^T tile; all acc
// preloaded with bias (kills epilogue adds). ~280 fewer scalar ops/warp/iter.

#define NTHR  256
#define TM    128
#define NS    51
#define NB    50
#define BATCH 16384
#define HID   128

// tile: 128 rows x 256 B; byte(r,k) = r*256 + 16*((k>>3)^(r&7)) + (k&7)*2
#define TILE_B   32768
#define OFF_W2   0
#define OFF_W3   (1 * TILE_B)
#define OFF_W1T  (2 * TILE_B)   // 128 n-rows x 16 k (k=0:w1a, k=1:w1b, rest 0)
#define OFF_MISC (3 * TILE_B)   // 98304
// float-indexed misc: [0,128) B1 | [128,256) B2 | [256,384) B3
// [384,512) W4 | [512,640) X | [640,768) H | [768,820) CCW(52) | [820] b4
#define SMEM_TOTAL (OFF_MISC + 832 * 4)

__device__ __forceinline__ void mma_bf16(float* c, const uint32_t* a,
                                         uint32_t b0, uint32_t b1) {
    asm volatile(
        "mma.sync.aligned.m16n8k16.row.col.f32.bf16.bf16.f32 "
        "{%0,%1,%2,%3}, {%4,%5,%6,%7}, {%8,%9}, {%0,%1,%2,%3};"
        : "+f"(c[0]), "+f"(c[1]), "+f"(c[2]), "+f"(c[3])
        : "r"(a[0]), "r"(a[1]), "r"(a[2]), "r"(a[3]), "r"(b0), "r"(b1));
}

#define LDSM_X4(r, addr) \
    asm volatile("ldmatrix.sync.aligned.m8n8.x4.shared.b16 {%0,%1,%2,%3}, [%4];" \
        : "=r"((r)[0]), "=r"((r)[1]), "=r"((r)[2]), "=r"((r)[3]) : "r"(addr))

__device__ __forceinline__ uint32_t smem_to_u32(const void* p) {
    uint32_t a;
    asm("{ .reg .u64 t; cvta.to.shared.u64 t, %1; cvt.u32.u64 %0, t; }" : "=r"(a) : "l"(p));
    return a;
}

// pack two fp32 -> bf16x2 (v0 in low half)
__device__ __forceinline__ uint32_t pack_bf16(float v0, float v1) {
    uint32_t r;
    asm("cvt.rn.bf16x2.f32 %0, %1, %2;" : "=r"(r) : "f"(v1), "f"(v0));
    return r;
}

__global__ void __launch_bounds__(NTHR, 1)
monnn_kernel(const float* __restrict__ x,  const float* __restrict__ h,
             const float* __restrict__ w1, const float* __restrict__ b1,
             const float* __restrict__ w2, const float* __restrict__ b2,
             const float* __restrict__ w3, const float* __restrict__ b3,
             const float* __restrict__ w4, const float* __restrict__ b4,
             float* __restrict__ out) {
    extern __shared__ char smem[];
    float* FM  = (float*)(smem + OFF_MISC);
    float* sB1 = FM;          float* sB2 = FM + 128;
    float* sB3 = FM + 256;    float* sW4 = FM + 384;
    float* sX  = FM + 512;    float* sH  = FM + 640;
    float* sCCW = FM + 768;   // 52 entries

    const int tid  = threadIdx.x;
    const int wid  = tid >> 5;
    const int lane = tid & 31;
    const int mbase = wid * 16;           // warp m-strip (8 warps x 16 rows)
    const int bbase = blockIdx.x * TM;

    // ---- prologue: misc params ----
    if (tid < 128) {
        sB1[tid] = b1[tid]; sB2[tid] = b2[tid]; sB3[tid] = b3[tid];
        sW4[tid] = w4[tid];
        sX[tid] = x[bbase + tid]; sH[tid] = h[bbase + tid];
    }
    if (tid < 52) {  // Clenshaw-Curtis weights; [51]=0 pads the odd pair
        float acw = 0.0f;
        if (tid <= NB) {
            #pragma unroll 1
            for (int i = 0; i <= NB; i++) {
                float Wi = (i == 0) ? 1.0f : ((i & 1) ? 0.0f : 2.0f / (1.0f - (float)(i * i)));
                acw = fmaf(cospif((float)(i * tid) / (float)NB), Wi, acw);
            }
            acw *= 2.0f / (float)NB;
            if (tid == 0 || tid == NB) acw *= 0.5f;
        }
        sCCW[tid] = acw;
    }
    if (tid == 0) FM[820] = b4[0];

    // ---- prologue: zero W1T tile, then fill k=0,1 ----
    for (int i = tid; i < TILE_B / 4; i += NTHR)
        ((uint32_t*)(smem + OFF_W1T))[i] = 0u;
    __syncthreads();   // zero visible before partial fill
    if (tid < 128) {
        int j = tid;
        // k-pair (0,1) -> word at row j, chunk (0^(j&7)), word 0
        uint32_t off = OFF_W1T + (uint32_t)j * 256u + 16u * (uint32_t)(j & 7);
        *(uint32_t*)(smem + off) = pack_bf16(w1[j], w1[128 + j]);
    }

    // ---- prologue: W2,W3 -> transposed bf16 swizzled tiles Wt[j][k] ----
    for (int t = tid; t < 2 * 8192; t += NTHR) {
        int mtx = t >> 13;
        int r   = t & 8191;
        int kp  = r >> 7;           // k-pair index
        int j   = r & 127;
        int k   = kp * 2;
        const float* W = mtx ? w3 : w2;
        float v0 = W[k * 128 + j];
        float v1 = W[(k + 1) * 128 + j];
        uint32_t hp = pack_bf16(v0, v1);
        uint32_t off = (mtx ? OFF_W3 : OFF_W2)
                     + (uint32_t)j * 256u
                     + 16u * ((uint32_t)(k >> 3) ^ (uint32_t)(j & 7))
                     + (uint32_t)(kp & 3) * 4u;
        *(uint32_t*)(smem + off) = hp;
    }
    __syncthreads();

    // ---- per-thread constants (validated R5-R9) ----
    const int r0 = mbase + (lane >> 2);        // frag row 0
    const int r1 = r0 + 8;                     // frag row 1
    const int kq = (lane & 3) * 2;             // frag col/k pair base
    const float xm0 = sX[r0], xm1 = sX[r1];
    const float hm0 = sH[r0], hm1 = sH[r1];
    const float b4v = FM[820];
    const uint32_t sb = smem_to_u32(smem);
    const int lane7 = lane & 7;
    // B-ldmatrix lane constants: mi = lane>>3 -> n-tile 2g+(mi>>1), chunk 2ks+(mi&1)
    const uint32_t nB  = (uint32_t)(8 * ((lane >> 3) >> 1) + lane7);
    const uint32_t n7B = nB & 7u;
    const uint32_t cB  = (uint32_t)((lane >> 3) & 1);
    const uint32_t rowB = nB * 256u;           // + g*4096
    const uint32_t swbL1 = (cB ^ n7B) * 16u;   // L1 B swizzle (ks=0)
    const bool aLane = ((lane & 3) == 0);      // lanes holding L1 A data (k=0,1)

    float z0 = 0.0f, z1 = 0.0f;

    #pragma unroll 1
    for (int sp = 0; sp < 26; sp++) {
        const int s0 = 2 * sp, s1 = 2 * sp + 1;
        const float tS0 = (cospif((float)s0 / (float)NB) + 1.0f) * 0.5f;
        const float tS1 = (cospif((float)s1 / (float)NB) + 1.0f) * 0.5f;

        // ---- L1 A-frags: A[m][0]=xs, A[m][1]=hm (k>=2 zero) ----
        uint32_t aF0[4], aF1[4];
        aF0[0] = aLane ? pack_bf16(xm0 * tS0, hm0) : 0u;
        aF0[1] = aLane ? pack_bf16(xm1 * tS0, hm1) : 0u;
        aF1[0] = aLane ? pack_bf16(xm0 * tS1, hm0) : 0u;
        aF1[1] = aLane ? pack_bf16(xm1 * tS1, hm1) : 0u;
        aF0[2] = aF0[3] = aF1[2] = aF1[3] = 0u;

        // ================= layer 1 via MMA (g2 blocks) =================
        uint32_t aIn0[32], aIn1[32];
        #pragma unroll
        for (int g2 = 0; g2 < 4; g2++) {
            float acc[8][4];
            #pragma unroll
            for (int ti = 0; ti < 4; ti++) {   // bias-preloaded C
                int n0 = 8 * (4 * g2 + ti) + kq;
                float2 bv = *(const float2*)&sB1[n0];
                acc[2*ti][0] = bv.x; acc[2*ti][1] = bv.y;
                acc[2*ti][2] = bv.x; acc[2*ti][3] = bv.y;
                acc[2*ti+1][0] = bv.x; acc[2*ti+1][1] = bv.y;
                acc[2*ti+1][2] = bv.x; acc[2*ti+1][3] = bv.y;
            }
            uint32_t bqA[4], bqB[4];
            LDSM_X4(bqA, sb + OFF_W1T + rowB + (uint32_t)(2*g2)     * 4096u + swbL1);
            LDSM_X4(bqB, sb + OFF_W1T + rowB + (uint32_t)(2*g2 + 1) * 4096u + swbL1);
            mma_bf16(acc[0], aF0, bqA[0], bqA[1]);
            mma_bf16(acc[1], aF1, bqA[0], bqA[1]);
            mma_bf16(acc[2], aF0, bqA[2], bqA[3]);
            mma_bf16(acc[3], aF1, bqA[2], bqA[3]);
            mma_bf16(acc[4], aF0, bqB[0], bqB[1]);
            mma_bf16(acc[5], aF1, bqB[0], bqB[1]);
            mma_bf16(acc[6], aF0, bqB[2], bqB[3]);
            mma_bf16(acc[7], aF1, bqB[2], bqB[3]);
            #pragma unroll
            for (int ti = 0; ti < 4; ti++) {   // relu + pack -> L2 A-frags
                int t = 4 * g2 + ti;
                const float* A0 = acc[2 * ti];
                const float* A1 = acc[2 * ti + 1];
                aIn0[2*t]     = pack_bf16(fmaxf(A0[0], 0.0f), fmaxf(A0[1], 0.0f));
                aIn0[2*t + 1] = pack_bf16(fmaxf(A0[2], 0.0f), fmaxf(A0[3], 0.0f));
                aIn1[2*t]     = pack_bf16(fmaxf(A1[0], 0.0f), fmaxf(A1[1], 0.0f));
                aIn1[2*t + 1] = pack_bf16(fmaxf(A1[2], 0.0f), fmaxf(A1[3], 0.0f));
            }
        }

        // ================= layer 2 (g2 blocks, bias-preloaded) =================
        uint32_t af0[32], af1[32];
        #pragma unroll
        for (int g2 = 0; g2 < 4; g2++) {
            float acc[8][4];
            #pragma unroll
            for (int ti = 0; ti < 4; ti++) {
                int n0 = 8 * (4 * g2 + ti) + kq;
                float2 bv = *(const float2*)&sB2[n0];
                acc[2*ti][0] = bv.x; acc[2*ti][1] = bv.y;
                acc[2*ti][2] = bv.x; acc[2*ti][3] = bv.y;
                acc[2*ti+1][0] = bv.x; acc[2*ti+1][1] = bv.y;
                acc[2*ti+1][2] = bv.x; acc[2*ti+1][3] = bv.y;
            }
            #pragma unroll
            for (int ks = 0; ks < 8; ks++) {
                const uint32_t swb = (((uint32_t)(2 * ks) + cB) ^ n7B) * 16u;
                uint32_t bqA[4], bqB[4];
                LDSM_X4(bqA, sb + OFF_W2 + rowB + (uint32_t)(2*g2)     * 4096u + swb);
                LDSM_X4(bqB, sb + OFF_W2 + rowB + (uint32_t)(2*g2 + 1) * 4096u + swb);
                mma_bf16(acc[0], &aIn0[4*ks], bqA[0], bqA[1]);
                mma_bf16(acc[1], &aIn1[4*ks], bqA[0], bqA[1]);
                mma_bf16(acc[2], &aIn0[4*ks], bqA[2], bqA[3]);
                mma_bf16(acc[3], &aIn1[4*ks], bqA[2], bqA[3]);
                mma_bf16(acc[4], &aIn0[4*ks], bqB[0], bqB[1]);
                mma_bf16(acc[5], &aIn1[4*ks], bqB[0], bqB[1]);
                mma_bf16(acc[6], &aIn0[4*ks], bqB[2], bqB[3]);
                mma_bf16(acc[7], &aIn1[4*ks], bqB[2], bqB[3]);
            }
            #pragma unroll
            for (int ti = 0; ti < 4; ti++) {   // relu + pack -> L3 A-frags
                int t = 4 * g2 + ti;
                const float* A0 = acc[2 * ti];
                const float* A1 = acc[2 * ti + 1];
                af0[2*t]     = pack_bf16(fmaxf(A0[0], 0.0f), fmaxf(A0[1], 0.0f));
                af0[2*t + 1] = pack_bf16(fmaxf(A0[2], 0.0f), fmaxf(A0[3], 0.0f));
                af1[2*t]     = pack_bf16(fmaxf(A1[0], 0.0f), fmaxf(A1[1], 0.0f));
                af1[2*t + 1] = pack_bf16(fmaxf(A1[2], 0.0f), fmaxf(A1[3], 0.0f));
            }
        }

        // ============ layer 3 + fused layer 4 partials (bias-preloaded) ============
        float p00 = 0.0f, p01 = 0.0f, p10 = 0.0f, p11 = 0.0f;
        #pragma unroll
        for (int g2 = 0; g2 < 4; g2++) {
            float acc[8][4];
            #pragma unroll
            for (int ti = 0; ti < 4; ti++) {
                int n0 = 8 * (4 * g2 + ti) + kq;
                float2 bv = *(const float2*)&sB3[n0];
                acc[2*ti][0] = bv.x; acc[2*ti][1] = bv.y;
                acc[2*ti][2] = bv.x; acc[2*ti][3] = bv.y;
                acc[2*ti+1][0] = bv.x; acc[2*ti+1][1] = bv.y;
                acc[2*ti+1][2] = bv.x; acc[2*ti+1][3] = bv.y;
            }
            #pragma unroll
            for (int ks = 0; ks < 8; ks++) {
                const uint32_t swb = (((uint32_t)(2 * ks) + cB) ^ n7B) * 16u;
                uint32_t bqA[4], bqB[4];
                LDSM_X4(bqA, sb + OFF_W3 + rowB + (uint32_t)(2*g2)     * 4096u + swb);
                LDSM_X4(bqB, sb + OFF_W3 + rowB + (uint32_t)(2*g2 + 1) * 4096u + swb);
                mma_bf16(acc[0], &af0[4*ks], bqA[0], bqA[1]);
                mma_bf16(acc[1], &af1[4*ks], bqA[0], bqA[1]);
                mma_bf16(acc[2], &af0[4*ks], bqA[2], bqA[3]);
                mma_bf16(acc[3], &af1[4*ks], bqA[2], bqA[3]);
                mma_bf16(acc[4], &af0[4*ks], bqB[0], bqB[1]);
                mma_bf16(acc[5], &af1[4*ks], bqB[0], bqB[1]);
                mma_bf16(acc[6], &af0[4*ks], bqB[2], bqB[3]);
                mma_bf16(acc[7], &af1[4*ks], bqB[2], bqB[3]);
            }
            #pragma unroll
            for (int ti = 0; ti < 4; ti++) {   // L4 partials (bias inside acc)
                int n0 = 8 * (4 * g2 + ti) + kq;
                float2 w4v = *(const float2*)&sW4[n0];
                const float* A0 = acc[2 * ti];
                const float* A1 = acc[2 * ti + 1];
                p00 = fmaf(fmaxf(A0[0], 0.0f), w4v.x, p00);
                p00 = fmaf(fmaxf(A0[1], 0.0f), w4v.y, p00);
                p01 = fmaf(fmaxf(A0[2], 0.0f), w4v.x, p01);
                p01 = fmaf(fmaxf(A0[3], 0.0f), w4v.y, p01);
                p10 = fmaf(fmaxf(A1[0], 0.0f), w4v.x, p10);
                p10 = fmaf(fmaxf(A1[1], 0.0f), w4v.y, p10);
                p11 = fmaf(fmaxf(A1[2], 0.0f), w4v.x, p11);
                p11 = fmaf(fmaxf(A1[3], 0.0f), w4v.y, p11);
            }
        }

        // quad shfl-reduce (lanes of a quad share the same row)
        p00 += __shfl_xor_sync(0xFFFFFFFFu, p00, 1);
        p00 += __shfl_xor_sync(0xFFFFFFFFu, p00, 2);
        p01 += __shfl_xor_sync(0xFFFFFFFFu, p01, 1);
        p01 += __shfl_xor_sync(0xFFFFFFFFu, p01, 2);
        p10 += __shfl_xor_sync(0xFFFFFFFFu, p10, 1);
        p10 += __shfl_xor_sync(0xFFFFFFFFu, p10, 2);
        p11 += __shfl_xor_sync(0xFFFFFFFFu, p11, 1);
        p11 += __shfl_xor_sync(0xFFFFFFFFu, p11, 2);

        const float ccw0 = sCCW[s0], ccw1 = sCCW[s1];
        float v;
        v = p00 + b4v; z0 = fmaf(ccw0, ((v > 0.0f) ? v : expm1f(v)) + 1.0f, z0);
        v = p01 + b4v; z1 = fmaf(ccw0, ((v > 0.0f) ? v : expm1f(v)) + 1.0f, z1);
        v = p10 + b4v; z0 = fmaf(ccw1, ((v > 0.0f) ? v : expm1f(v)) + 1.0f, z0);
        v = p11 + b4v; z1 = fmaf(ccw1, ((v > 0.0f) ? v : expm1f(v)) + 1.0f, z1);
    }

    if ((lane & 3) == 0) {
        out[bbase + r0] = fmaf(z0, 0.5f * xm0, hm0);
        out[bbase + r1] = fmaf(z1, 0.5f * xm1, hm1);
    }
}

extern "C" void kernel_launch(void* const* d_in, const int* in_sizes, int n_in,
                              void* d_out, int out_size) {
    const float* x  = (const float*)d_in[0];
    const float* h  = (const float*)d_in[1];
    const float* w1 = (const float*)d_in[2];
    const float* b1 = (const float*)d_in[3];
    const float* w2 = (const float*)d_in[4];
    const float* b2 = (const float*)d_in[5];
    const float* w3 = (const float*)d_in[6];
    const float* b3 = (const float*)d_in[7];
    const float* w4 = (const float*)d_in[8];
    const float* b4 = (const float*)d_in[9];
    float* out = (float*)d_out;

    static int attr_set = 0;
    if (!attr_set) {
        cudaFuncSetAttribute(monnn_kernel,
                             cudaFuncAttributeMaxDynamicSharedMemorySize, SMEM_TOTAL);
        attr_set = 1;
    }
    monnn_kernel<<<BATCH / TM, NTHR, SMEM_TOTAL>>>(x, h, w1, b1, w2, b2, w3, b3, w4, b4, out);
}

// round 17
// speedup vs baseline: 1.3534x; 1.0783x over previous
#include <cuda_runtime.h>
#include <cuda_bf16.h>
#include <math.h>
#include <stdint.h>

// MonotonicNN via HMMA bf16, all layers on tensor core (R15 body), now with
// BALANCED decomposition: 3328 (b-tile, s-pair) units over 148 CTAs (all SMs
// busy; was 128 CTAs / 20 idle SMs). CTA accumulates z in regs while its
// units share a tile; flushes via atomicAdd to g_z; zero+combine kernels.

#define NTHR  256
#define TM    128
#define NS    51
#define NB    50
#define BATCH 16384
#define HID   128
#define NPAIR 26
#define NTILE (BATCH / TM)          // 128
#define NUNITS (NTILE * NPAIR)      // 3328
#define NCTA  148

// tile: 128 rows x 256 B; byte(r,k) = r*256 + 16*((k>>3)^(r&7)) + (k&7)*2
#define TILE_B   32768
#define OFF_W2   0
#define OFF_W3   (1 * TILE_B)
#define OFF_W1T  (2 * TILE_B)   // 128 n-rows x 16 k (k=0:w1a, k=1:w1b, rest 0)
#define OFF_MISC (3 * TILE_B)   // 98304
// float-indexed misc: [0,128) B1 | [128,256) B2 | [256,384) B3
// [384,512) W4 | [512,640) X | [640,768) H | [768,820) CCW(52) | [820] b4
#define SMEM_TOTAL (OFF_MISC + 832 * 4)

__device__ float g_z[BATCH];

__device__ __forceinline__ void mma_bf16(float* c, const uint32_t* a,
                                         uint32_t b0, uint32_t b1) {
    asm volatile(
        "mma.sync.aligned.m16n8k16.row.col.f32.bf16.bf16.f32 "
        "{%0,%1,%2,%3}, {%4,%5,%6,%7}, {%8,%9}, {%0,%1,%2,%3};"
        : "+f"(c[0]), "+f"(c[1]), "+f"(c[2]), "+f"(c[3])
        : "r"(a[0]), "r"(a[1]), "r"(a[2]), "r"(a[3]), "r"(b0), "r"(b1));
}

#define LDSM_X4(r, addr) \
    asm volatile("ldmatrix.sync.aligned.m8n8.x4.shared.b16 {%0,%1,%2,%3}, [%4];" \
        : "=r"((r)[0]), "=r"((r)[1]), "=r"((r)[2]), "=r"((r)[3]) : "r"(addr))

__device__ __forceinline__ uint32_t smem_to_u32(const void* p) {
    uint32_t a;
    asm("{ .reg .u64 t; cvta.to.shared.u64 t, %1; cvt.u32.u64 %0, t; }" : "=r"(a) : "l"(p));
    return a;
}

// pack two fp32 -> bf16x2 (v0 in low half)
__device__ __forceinline__ uint32_t pack_bf16(float v0, float v1) {
    uint32_t r;
    asm("cvt.rn.bf16x2.f32 %0, %1, %2;" : "=r"(r) : "f"(v1), "f"(v0));
    return r;
}

__global__ void zero_kernel() {
    g_z[blockIdx.x * 256 + threadIdx.x] = 0.0f;
}

__global__ void combine_kernel(const float* __restrict__ x,
                               const float* __restrict__ h,
                               float* __restrict__ out) {
    int b = blockIdx.x * 256 + threadIdx.x;
    out[b] = fmaf(g_z[b], 0.5f * x[b], h[b]);
}

__global__ void __launch_bounds__(NTHR, 1)
monnn_kernel(const float* __restrict__ x,  const float* __restrict__ h,
             const float* __restrict__ w1, const float* __restrict__ b1,
             const float* __restrict__ w2, const float* __restrict__ b2,
             const float* __restrict__ w3, const float* __restrict__ b3,
             const float* __restrict__ w4, const float* __restrict__ b4) {
    extern __shared__ char smem[];
    float* FM  = (float*)(smem + OFF_MISC);
    float* sB1 = FM;          float* sB2 = FM + 128;
    float* sB3 = FM + 256;    float* sW4 = FM + 384;
    float* sX  = FM + 512;    float* sH  = FM + 640;
    float* sCCW = FM + 768;   // 52 entries

    const int tid  = threadIdx.x;
    const int wid  = tid >> 5;
    const int lane = tid & 31;
    const int mbase = wid * 16;           // warp m-strip (8 warps x 16 rows)

    // ---- prologue: misc params ----
    if (tid < 128) {
        sB1[tid] = b1[tid]; sB2[tid] = b2[tid]; sB3[tid] = b3[tid];
        sW4[tid] = w4[tid];
    }
    if (tid < 52) {  // Clenshaw-Curtis weights; [51]=0 pads the odd pair
        float acw = 0.0f;
        if (tid <= NB) {
            #pragma unroll 1
            for (int i = 0; i <= NB; i++) {
                float Wi = (i == 0) ? 1.0f : ((i & 1) ? 0.0f : 2.0f / (1.0f - (float)(i * i)));
                acw = fmaf(cospif((float)(i * tid) / (float)NB), Wi, acw);
            }
            acw *= 2.0f / (float)NB;
            if (tid == 0 || tid == NB) acw *= 0.5f;
        }
        sCCW[tid] = acw;
    }
    if (tid == 0) FM[820] = b4[0];

    // ---- prologue: zero W1T tile, then fill k=0,1 ----
    for (int i = tid; i < TILE_B / 4; i += NTHR)
        ((uint32_t*)(smem + OFF_W1T))[i] = 0u;
    __syncthreads();   // zero visible before partial fill
    if (tid < 128) {
        int j = tid;
        uint32_t off = OFF_W1T + (uint32_t)j * 256u + 16u * (uint32_t)(j & 7);
        *(uint32_t*)(smem + off) = pack_bf16(w1[j], w1[128 + j]);
    }

    // ---- prologue: W2,W3 -> transposed bf16 swizzled tiles Wt[j][k] ----
    for (int t = tid; t < 2 * 8192; t += NTHR) {
        int mtx = t >> 13;
        int r   = t & 8191;
        int kp  = r >> 7;           // k-pair index
        int j   = r & 127;
        int k   = kp * 2;
        const float* W = mtx ? w3 : w2;
        float v0 = W[k * 128 + j];
        float v1 = W[(k + 1) * 128 + j];
        uint32_t hp = pack_bf16(v0, v1);
        uint32_t off = (mtx ? OFF_W3 : OFF_W2)
                     + (uint32_t)j * 256u
                     + 16u * ((uint32_t)(k >> 3) ^ (uint32_t)(j & 7))
                     + (uint32_t)(kp & 3) * 4u;
        *(uint32_t*)(smem + off) = hp;
    }
    __syncthreads();

    // ---- per-thread constants (validated R5-R15) ----
    const int r0 = mbase + (lane >> 2);        // frag row 0
    const int r1 = r0 + 8;                     // frag row 1
    const int kq = (lane & 3) * 2;             // frag col/k pair base
    const float b4v = FM[820];
    const uint32_t sb = smem_to_u32(smem);
    const int lane7 = lane & 7;
    // B-ldmatrix lane constants: mi = lane>>3 -> n-tile 2g+(mi>>1), chunk 2ks+(mi&1)
    const uint32_t nB  = (uint32_t)(8 * ((lane >> 3) >> 1) + lane7);
    const uint32_t n7B = nB & 7u;
    const uint32_t cB  = (uint32_t)((lane >> 3) & 1);
    const uint32_t rowB = nB * 256u;           // + g*4096
    const uint32_t swbL1 = (cB ^ n7B) * 16u;   // L1 B swizzle (ks=0)
    const bool aLane = ((lane & 3) == 0);      // lanes holding L1 A data (k=0,1)

    // ---- balanced unit range: units = (tile, s-pair) ----
    int u = (NUNITS * blockIdx.x) / NCTA;
    const int u1 = (NUNITS * (blockIdx.x + 1)) / NCTA;

    while (u < u1) {
        const int tile  = u / NPAIR;
        const int bbase = tile * TM;

        __syncthreads();   // all warps done reading previous sX/sH
        if (tid < 128) {
            sX[tid] = x[bbase + tid];
            sH[tid] = h[bbase + tid];
        }
        __syncthreads();   // new sX/sH visible

        const float xm0 = sX[r0], xm1 = sX[r1];
        const float hm0 = sH[r0], hm1 = sH[r1];
        float z0 = 0.0f, z1 = 0.0f;

        int uend = (tile + 1) * NPAIR;
        if (uend > u1) uend = u1;

        #pragma unroll 1
        for (; u < uend; u++) {
            const int sp = u - tile * NPAIR;
            const int s0 = 2 * sp, s1 = 2 * sp + 1;
            const float tS0 = (cospif((float)s0 / (float)NB) + 1.0f) * 0.5f;
            const float tS1 = (cospif((float)s1 / (float)NB) + 1.0f) * 0.5f;

            // ---- L1 A-frags: A[m][0]=xs, A[m][1]=hm (k>=2 zero) ----
            uint32_t aF0[4], aF1[4];
            aF0[0] = aLane ? pack_bf16(xm0 * tS0, hm0) : 0u;
            aF0[1] = aLane ? pack_bf16(xm1 * tS0, hm1) : 0u;
            aF1[0] = aLane ? pack_bf16(xm0 * tS1, hm0) : 0u;
            aF1[1] = aLane ? pack_bf16(xm1 * tS1, hm1) : 0u;
            aF0[2] = aF0[3] = aF1[2] = aF1[3] = 0u;

            // ================= layer 1 via MMA (g2 blocks) =================
            uint32_t aIn0[32], aIn1[32];
            #pragma unroll
            for (int g2 = 0; g2 < 4; g2++) {
                float acc[8][4];
                #pragma unroll
                for (int ti = 0; ti < 4; ti++) {   // bias-preloaded C
                    int n0 = 8 * (4 * g2 + ti) + kq;
                    float2 bv = *(const float2*)&sB1[n0];
                    acc[2*ti][0] = bv.x; acc[2*ti][1] = bv.y;
                    acc[2*ti][2] = bv.x; acc[2*ti][3] = bv.y;
                    acc[2*ti+1][0] = bv.x; acc[2*ti+1][1] = bv.y;
                    acc[2*ti+1][2] = bv.x; acc[2*ti+1][3] = bv.y;
                }
                uint32_t bqA[4], bqB[4];
                LDSM_X4(bqA, sb + OFF_W1T + rowB + (uint32_t)(2*g2)     * 4096u + swbL1);
                LDSM_X4(bqB, sb + OFF_W1T + rowB + (uint32_t)(2*g2 + 1) * 4096u + swbL1);
                mma_bf16(acc[0], aF0, bqA[0], bqA[1]);
                mma_bf16(acc[1], aF1, bqA[0], bqA[1]);
                mma_bf16(acc[2], aF0, bqA[2], bqA[3]);
                mma_bf16(acc[3], aF1, bqA[2], bqA[3]);
                mma_bf16(acc[4], aF0, bqB[0], bqB[1]);
                mma_bf16(acc[5], aF1, bqB[0], bqB[1]);
                mma_bf16(acc[6], aF0, bqB[2], bqB[3]);
                mma_bf16(acc[7], aF1, bqB[2], bqB[3]);
                #pragma unroll
                for (int ti = 0; ti < 4; ti++) {   // relu + pack -> L2 A-frags
                    int t = 4 * g2 + ti;
                    const float* A0 = acc[2 * ti];
                    const float* A1 = acc[2 * ti + 1];
                    aIn0[2*t]     = pack_bf16(fmaxf(A0[0], 0.0f), fmaxf(A0[1], 0.0f));
                    aIn0[2*t + 1] = pack_bf16(fmaxf(A0[2], 0.0f), fmaxf(A0[3], 0.0f));
                    aIn1[2*t]     = pack_bf16(fmaxf(A1[0], 0.0f), fmaxf(A1[1], 0.0f));
                    aIn1[2*t + 1] = pack_bf16(fmaxf(A1[2], 0.0f), fmaxf(A1[3], 0.0f));
                }
            }

            // ================= layer 2 (g2 blocks, bias-preloaded) =================
            uint32_t af0[32], af1[32];
            #pragma unroll
            for (int g2 = 0; g2 < 4; g2++) {
                float acc[8][4];
                #pragma unroll
                for (int ti = 0; ti < 4; ti++) {
                    int n0 = 8 * (4 * g2 + ti) + kq;
                    float2 bv = *(const float2*)&sB2[n0];
                    acc[2*ti][0] = bv.x; acc[2*ti][1] = bv.y;
                    acc[2*ti][2] = bv.x; acc[2*ti][3] = bv.y;
                    acc[2*ti+1][0] = bv.x; acc[2*ti+1][1] = bv.y;
                    acc[2*ti+1][2] = bv.x; acc[2*ti+1][3] = bv.y;
                }
                #pragma unroll
                for (int ks = 0; ks < 8; ks++) {
                    const uint32_t swb = (((uint32_t)(2 * ks) + cB) ^ n7B) * 16u;
                    uint32_t bqA[4], bqB[4];
                    LDSM_X4(bqA, sb + OFF_W2 + rowB + (uint32_t)(2*g2)     * 4096u + swb);
                    LDSM_X4(bqB, sb + OFF_W2 + rowB + (uint32_t)(2*g2 + 1) * 4096u + swb);
                    mma_bf16(acc[0], &aIn0[4*ks], bqA[0], bqA[1]);
                    mma_bf16(acc[1], &aIn1[4*ks], bqA[0], bqA[1]);
                    mma_bf16(acc[2], &aIn0[4*ks], bqA[2], bqA[3]);
                    mma_bf16(acc[3], &aIn1[4*ks], bqA[2], bqA[3]);
                    mma_bf16(acc[4], &aIn0[4*ks], bqB[0], bqB[1]);
                    mma_bf16(acc[5], &aIn1[4*ks], bqB[0], bqB[1]);
                    mma_bf16(acc[6], &aIn0[4*ks], bqB[2], bqB[3]);
                    mma_bf16(acc[7], &aIn1[4*ks], bqB[2], bqB[3]);
                }
                #pragma unroll
                for (int ti = 0; ti < 4; ti++) {   // relu + pack -> L3 A-frags
                    int t = 4 * g2 + ti;
                    const float* A0 = acc[2 * ti];
                    const float* A1 = acc[2 * ti + 1];
                    af0[2*t]     = pack_bf16(fmaxf(A0[0], 0.0f), fmaxf(A0[1], 0.0f));
                    af0[2*t + 1] = pack_bf16(fmaxf(A0[2], 0.0f), fmaxf(A0[3], 0.0f));
                    af1[2*t]     = pack_bf16(fmaxf(A1[0], 0.0f), fmaxf(A1[1], 0.0f));
                    af1[2*t + 1] = pack_bf16(fmaxf(A1[2], 0.0f), fmaxf(A1[3], 0.0f));
                }
            }

            // ========= layer 3 + fused layer 4 partials (bias-preloaded) =========
            float p00 = 0.0f, p01 = 0.0f, p10 = 0.0f, p11 = 0.0f;
            #pragma unroll
            for (int g2 = 0; g2 < 4; g2++) {
                float acc[8][4];
                #pragma unroll
                for (int ti = 0; ti < 4; ti++) {
                    int n0 = 8 * (4 * g2 + ti) + kq;
                    float2 bv = *(const float2*)&sB3[n0];
                    acc[2*ti][0] = bv.x; acc[2*ti][1] = bv.y;
                    acc[2*ti][2] = bv.x; acc[2*ti][3] = bv.y;
                    acc[2*ti+1][0] = bv.x; acc[2*ti+1][1] = bv.y;
                    acc[2*ti+1][2] = bv.x; acc[2*ti+1][3] = bv.y;
                }
                #pragma unroll
                for (int ks = 0; ks < 8; ks++) {
                    const uint32_t swb = (((uint32_t)(2 * ks) + cB) ^ n7B) * 16u;
                    uint32_t bqA[4], bqB[4];
                    LDSM_X4(bqA, sb + OFF_W3 + rowB + (uint32_t)(2*g2)     * 4096u + swb);
                    LDSM_X4(bqB, sb + OFF_W3 + rowB + (uint32_t)(2*g2 + 1) * 4096u + swb);
                    mma_bf16(acc[0], &af0[4*ks], bqA[0], bqA[1]);
                    mma_bf16(acc[1], &af1[4*ks], bqA[0], bqA[1]);
                    mma_bf16(acc[2], &af0[4*ks], bqA[2], bqA[3]);
                    mma_bf16(acc[3], &af1[4*ks], bqA[2], bqA[3]);
                    mma_bf16(acc[4], &af0[4*ks], bqB[0], bqB[1]);
                    mma_bf16(acc[5], &af1[4*ks], bqB[0], bqB[1]);
                    mma_bf16(acc[6], &af0[4*ks], bqB[2], bqB[3]);
                    mma_bf16(acc[7], &af1[4*ks], bqB[2], bqB[3]);
                }
                #pragma unroll
                for (int ti = 0; ti < 4; ti++) {   // L4 partials (bias inside acc)
                    int n0 = 8 * (4 * g2 + ti) + kq;
                    float2 w4v = *(const float2*)&sW4[n0];
                    const float* A0 = acc[2 * ti];
                    const float* A1 = acc[2 * ti + 1];
                    p00 = fmaf(fmaxf(A0[0], 0.0f), w4v.x, p00);
                    p00 = fmaf(fmaxf(A0[1], 0.0f), w4v.y, p00);
                    p01 = fmaf(fmaxf(A0[2], 0.0f), w4v.x, p01);
                    p01 = fmaf(fmaxf(A0[3], 0.0f), w4v.y, p01);
                    p10 = fmaf(fmaxf(A1[0], 0.0f), w4v.x, p10);
                    p10 = fmaf(fmaxf(A1[1], 0.0f), w4v.y, p10);
                    p11 = fmaf(fmaxf(A1[2], 0.0f), w4v.x, p11);
                    p11 = fmaf(fmaxf(A1[3], 0.0f), w4v.y, p11);
                }
            }

            // quad shfl-reduce (lanes of a quad share the same row)
            p00 += __shfl_xor_sync(0xFFFFFFFFu, p00, 1);
            p00 += __shfl_xor_sync(0xFFFFFFFFu, p00, 2);
            p01 += __shfl_xor_sync(0xFFFFFFFFu, p01, 1);
            p01 += __shfl_xor_sync(0xFFFFFFFFu, p01, 2);
            p10 += __shfl_xor_sync(0xFFFFFFFFu, p10, 1);
            p10 += __shfl_xor_sync(0xFFFFFFFFu, p10, 2);
            p11 += __shfl_xor_sync(0xFFFFFFFFu, p11, 1);
            p11 += __shfl_xor_sync(0xFFFFFFFFu, p11, 2);

            const float ccw0 = sCCW[s0], ccw1 = sCCW[s1];
            float v;
            v = p00 + b4v; z0 = fmaf(ccw0, ((v > 0.0f) ? v : expm1f(v)) + 1.0f, z0);
            v = p01 + b4v; z1 = fmaf(ccw0, ((v > 0.0f) ? v : expm1f(v)) + 1.0f, z1);
            v = p10 + b4v; z0 = fmaf(ccw1, ((v > 0.0f) ? v : expm1f(v)) + 1.0f, z0);
            v = p11 + b4v; z1 = fmaf(ccw1, ((v > 0.0f) ? v : expm1f(v)) + 1.0f, z1);
        }

        // ---- flush this tile's contribution (lanes of each quad agree) ----
        if ((lane & 3) == 0) {
            atomicAdd(&g_z[bbase + r0], z0);
            atomicAdd(&g_z[bbase + r1], z1);
        }
    }
}

extern "C" void kernel_launch(void* const* d_in, const int* in_sizes, int n_in,
                              void* d_out, int out_size) {
    const float* x  = (const float*)d_in[0];
    const float* h  = (const float*)d_in[1];
    const float* w1 = (const float*)d_in[2];
    const float* b1 = (const float*)d_in[3];
    const float* w2 = (const float*)d_in[4];
    const float* b2 = (const float*)d_in[5];
    const float* w3 = (const float*)d_in[6];
    const float* b3 = (const float*)d_in[7];
    const float* w4 = (const float*)d_in[8];
    const float* b4 = (const float*)d_in[9];
    float* out = (float*)d_out;

    static int attr_set = 0;
    if (!attr_set) {
        cudaFuncSetAttribute(monnn_kernel,
                             cudaFuncAttributeMaxDynamicSharedMemorySize, SMEM_TOTAL);
        attr_set = 1;
    }
    zero_kernel<<<BATCH / 256, 256>>>();
    monnn_kernel<<<NCTA, NTHR, SMEM_TOTAL>>>(x, h, w1, b1, w2, b2, w3, b3, w4, b4);
    combine_kernel<<<BATCH / 256, 256>>>(x, h, out);
}